// round 2
// baseline (speedup 1.0000x reference)
#include <cuda_runtime.h>
#include <cstdint>

#define NB   128
#define NTH  256

// SMEM float offsets
#define W_OFF    0        // 13312 floats: weights [13 chunks][128 k][8 slots]
#define IN_OFF   13312    // 16384: double-buffered input chunk [2][128][64]
#define RED_OFF  29696    // 9216: reduction 32 rows x 288 (padded)
#define XS_OFF   38912    // 768: membrane potentials x, [12 cols][64 b]
#define BIAS_OFF 39680    // 16
#define SMEM_FLOATS 39696
#define SMEM_BYTES  (SMEM_FLOATS*4)

__device__ float    g_rbuf[2][1536*64];   // rates, [k][b]
__device__ float    g_XT[499*128*64];     // X transposed/padded: [s][d(128)][b]
__device__ float    g_Rm1[499*512*64];    // r_m1 history [s][k][b]
__device__ unsigned g_bar_count;
__device__ unsigned g_bar_gen;

__device__ __forceinline__ void cp16(float* sdst, const float* gsrc) {
    unsigned s = (unsigned)__cvta_generic_to_shared(sdst);
    asm volatile("cp.async.cg.shared.global [%0], [%1], 16;\n" :: "r"(s), "l"(gsrc) : "memory");
}

__device__ __forceinline__ void stage(float* dst, const float* src, int tid) {
    for (int i = tid; i < 2048; i += NTH) cp16(dst + i*4, src + i*4);
    asm volatile("cp.async.commit_group;\n" ::: "memory");
}

__device__ __forceinline__ void grid_barrier() {
    __syncthreads();
    if (threadIdx.x == 0) {
        __threadfence();
        unsigned old = *(volatile unsigned*)&g_bar_gen;
        if (atomicAdd(&g_bar_count, 1u) == NB - 1u) {
            atomicExch(&g_bar_count, 0u);
            __threadfence();
            atomicAdd(&g_bar_gen, 1u);
        } else {
            while (*(volatile unsigned*)&g_bar_gen == old) { }
        }
    }
    __syncthreads();
}

__device__ __forceinline__ void chunk_fma(float (&acc)[16], const float* rin,
                                          const float* wc, int ks) {
    #pragma unroll
    for (int t = 0; t < 16; t++) {
        int kk = ks*16 + t;
        float4 rv = *(const float4*)(rin + kk*64);
        float4 wv = *(const float4*)(wc + kk*8);
        acc[0]  += rv.x*wv.x; acc[1]  += rv.x*wv.y; acc[2]  += rv.x*wv.z; acc[3]  += rv.x*wv.w;
        acc[4]  += rv.y*wv.x; acc[5]  += rv.y*wv.y; acc[6]  += rv.y*wv.z; acc[7]  += rv.y*wv.w;
        acc[8]  += rv.z*wv.x; acc[9]  += rv.z*wv.y; acc[10] += rv.z*wv.z; acc[11] += rv.z*wv.w;
        acc[12] += rv.w*wv.x; acc[13] += rv.w*wv.y; acc[14] += rv.w*wv.z; acc[15] += rv.w*wv.w;
    }
}

__global__ void __launch_bounds__(NTH, 1)
rnn_kernel(const float* __restrict__ X,
           const float* __restrict__ W_rec_m1, const float* __restrict__ W_rec_pmd,
           const float* __restrict__ W_rec_s1,
           const float* __restrict__ b_m1, const float* __restrict__ b_pmd,
           const float* __restrict__ b_s1,
           const float* __restrict__ W_pmd_m1, const float* __restrict__ W_s1_m1,
           const float* __restrict__ W_m1_pmd,
           const float* __restrict__ W_in_pmd, const float* __restrict__ W_in_s1,
           const float* __restrict__ W_out,
           float* __restrict__ out)
{
    extern __shared__ float sm[];
    const int tid = threadIdx.x;
    const int g   = blockIdx.x;
    float* w_s    = sm + W_OFF;
    float* in_s   = sm + IN_OFF;
    float* red_s  = sm + RED_OFF;
    float* xs     = sm + XS_OFF;
    float* bias_s = sm + BIAS_OFF;
    const int j0  = 4*g;

    // ---- phase 0: init globals ----
    for (int i = g*NTH + tid; i < 2*1536*64; i += NB*NTH) ((float*)g_rbuf)[i] = 0.f;
    for (int i = g*NTH + tid; i < 499*128*64; i += NB*NTH) {
        int b = i & 63, d = (i >> 6) & 127, s = i >> 13;
        g_XT[i] = (d < 100) ? X[((s+1)*64 + b)*100 + d] : 0.f;
    }

    // ---- weights into SMEM: w_s[c][k][slot], slot = jg*4+jj ----
    // c0-3 src r_m1:  jg0=W_m1_pmd(->pmd) jg1=W_rec_m1(->m1)
    // c4-7 src r_pmd: jg0=W_rec_pmd(->pmd) jg1=W_pmd_m1(->m1)
    // c8-11 src r_s1: jg0=W_s1_m1(->m1)   jg1=W_rec_s1(->s1)
    // c12  src Xt:    jg0=W_in_pmd(->pmd) jg1=W_in_s1(->s1)
    for (int idx = tid; idx < 13312; idx += NTH) {
        int c = idx >> 10, rem = idx & 1023, k = rem >> 3, slot = rem & 7;
        int jgq = slot >> 2, jj = slot & 3;
        float v;
        if (c < 4) { int kk = c*128 + k;
            v = jgq ? W_rec_m1[(j0+jj)*512 + kk] : W_m1_pmd[(j0+jj)*512 + kk];
        } else if (c < 8) { int kk = (c-4)*128 + k;
            v = jgq ? W_pmd_m1[(j0+jj)*512 + kk] : W_rec_pmd[(j0+jj)*512 + kk];
        } else if (c < 12) { int kk = (c-8)*128 + k;
            v = jgq ? W_rec_s1[(j0+jj)*512 + kk] : W_s1_m1[(j0+jj)*512 + kk];
        } else {
            v = (k < 100) ? (jgq ? W_in_s1[(j0+jj)*100 + k] : W_in_pmd[(j0+jj)*100 + k]) : 0.f;
        }
        w_s[idx] = v;
    }
    if (tid < 12) {
        int jj = tid & 3;
        bias_s[tid] = (tid < 4) ? b_m1[j0+jj] : ((tid < 8) ? b_pmd[j0+jj] : b_s1[j0+jj]);
    }
    for (int i = tid; i < 768; i += NTH) xs[i] = 0.f;

    grid_barrier();

    const int ks   = tid >> 5;
    const int lane = tid & 31;
    const int jg   = lane >> 4;
    const int b0   = (lane & 15) * 4;

    // ---- the 499-step scan ----
    for (int s = 0; s < 499; s++) {
        const int cur = s & 1;
        const float* rb = g_rbuf[cur];

        stage(in_s, rb, tid);
        asm volatile("cp.async.wait_group 0;\n" ::: "memory");
        __syncthreads();

        float accP[16], accS[16], accX[16];
        #pragma unroll
        for (int i = 0; i < 16; i++) { accP[i] = 0.f; accS[i] = 0.f; accX[i] = 0.f; }

        for (int c = 0; c < 8; c++) {
            stage(in_s + ((c+1)&1)*8192, rb + (c+1)*8192, tid);
            chunk_fma(accP, in_s + (c&1)*8192 + b0, w_s + c*1024 + jg*4, ks);
            asm volatile("cp.async.wait_group 0;\n" ::: "memory");
            __syncthreads();
        }
        for (int c = 8; c < 12; c++) {
            const float* src = (c < 11) ? (rb + (c+1)*8192) : (g_XT + s*8192);
            stage(in_s + ((c+1)&1)*8192, src, tid);
            chunk_fma(accS, in_s + (c&1)*8192 + b0, w_s + c*1024 + jg*4, ks);
            asm volatile("cp.async.wait_group 0;\n" ::: "memory");
            __syncthreads();
        }
        chunk_fma(accX, in_s + 0*8192 + b0, w_s + 12*1024 + jg*4, ks);

        // merge accX: jg0 -> pmd(accP), jg1 -> s1(accS)
        #pragma unroll
        for (int i = 0; i < 16; i++) {
            if (jg == 0) accP[i] += accX[i]; else accS[i] += accX[i];
        }

        // dump partials. rows: P=(ks*2+jg)*2, S=+1. elem(b,jj)=b*4+(b>>3)*4+jj
        {
            int rowP = (ks*2 + jg)*2, rowS = rowP + 1;
            #pragma unroll
            for (int bi = 0; bi < 4; bi++) {
                int b = b0 + bi;
                int e = b*4 + ((b >> 3) << 2);
                *(float4*)(red_s + rowP*288 + e) = make_float4(accP[bi*4+0], accP[bi*4+1], accP[bi*4+2], accP[bi*4+3]);
                *(float4*)(red_s + rowS*288 + e) = make_float4(accS[bi*4+0], accS[bi*4+1], accS[bi*4+2], accS[bi*4+3]);
            }
        }
        __syncthreads();

        // reduce across 8 K-slice warps, leaky update, tanh, publish
        float* rnew = g_rbuf[cur ^ 1];
        for (int idx = tid; idx < 768; idx += NTH) {
            int col = idx >> 6, b = idx & 63, jj = col & 3;
            int e = b*4 + ((b >> 3) << 2) + jj;
            float sum = 0.f;
            if (col < 4) {            // m1: jg0-S rows 4q+1, jg1-P rows 4q+2
                #pragma unroll
                for (int q = 0; q < 8; q++)
                    sum += red_s[(4*q+1)*288 + e] + red_s[(4*q+2)*288 + e];
            } else if (col < 8) {     // pmd: jg0-P rows 4q
                #pragma unroll
                for (int q = 0; q < 8; q++) sum += red_s[(4*q+0)*288 + e];
            } else {                  // s1: jg1-S rows 4q+3
                #pragma unroll
                for (int q = 0; q < 8; q++) sum += red_s[(4*q+3)*288 + e];
            }
            float x = xs[idx];
            x = 0.9f*x + 0.1f*(sum + bias_s[col]);
            xs[idx] = x;
            float r = tanhf(x);
            int grow = (col < 4) ? (j0 + col)
                     : (col < 8) ? (512 + j0 + col - 4)
                                 : (1024 + j0 + col - 8);
            rnew[grow*64 + b] = r;
            if (col < 4) g_Rm1[(s*512 + j0 + col)*64 + b] = r;
        }
        grid_barrier();
    }

    // ---- epilogue: out[t][b][o] = sum_k Rm1[t][k][b] * W_out[o][k] ----
    for (int i = tid; i < 5120; i += NTH) w_s[i] = W_out[i];
    for (int t = g; t < 499; t += NB) {
        float acc3[3] = {0.f, 0.f, 0.f};
        for (int h = 0; h < 2; h++) {
            __syncthreads();
            const float4* src = (const float4*)(g_Rm1 + (t*512 + h*256)*64);
            for (int i = tid; i < 4096; i += NTH) ((float4*)in_s)[i] = src[i];
            __syncthreads();
            #pragma unroll
            for (int pi = 0; pi < 3; pi++) {
                int p = tid + pi*256;
                if (p < 640) {
                    int o = p >> 6, b = p & 63;
                    float sv = 0.f;
                    #pragma unroll 8
                    for (int k = 0; k < 256; k++)
                        sv += in_s[k*64 + b] * w_s[o*512 + h*256 + k];
                    acc3[pi] += sv;
                }
            }
        }
        #pragma unroll
        for (int pi = 0; pi < 3; pi++) {
            int p = tid + pi*256;
            if (p < 640) {
                int o = p >> 6, b = p & 63;
                out[t*640 + b*10 + o] = acc3[pi];
            }
        }
    }
}

extern "C" void kernel_launch(void* const* d_in, const int* in_sizes, int n_in,
                              void* d_out, int out_size) {
    cudaFuncSetAttribute(rnn_kernel, cudaFuncAttributeMaxDynamicSharedMemorySize, SMEM_BYTES);
    rnn_kernel<<<NB, NTH, SMEM_BYTES>>>(
        (const float*)d_in[0],  (const float*)d_in[1],  (const float*)d_in[2],
        (const float*)d_in[3],  (const float*)d_in[4],  (const float*)d_in[5],
        (const float*)d_in[6],  (const float*)d_in[7],  (const float*)d_in[8],
        (const float*)d_in[9],  (const float*)d_in[10], (const float*)d_in[11],
        (const float*)d_in[12], (float*)d_out);
}